// round 4
// baseline (speedup 1.0000x reference)
#include <cuda_runtime.h>
#include <math.h>

#define B_  1024
#define L_  50
#define D_  4
#define H_  512
#define T_  30
#define N4H 2048   // 4*H
#define CW  516    // H + D (comb/attn weight row stride)

// ---------------- persistent device state (allocation-free scratch) ----------------
__device__ __align__(16) float g_hA[B_ * H_];
__device__ __align__(16) float g_hB[B_ * H_];
__device__ __align__(16) float g_c[B_ * H_];
__device__ __align__(16) float g_enc[B_ * L_ * H_];    // encoder outputs (B, L, H)
__device__ __align__(16) float g_attn[B_ * H_];
__device__ __align__(16) float g_comb[B_ * H_];
__device__ __align__(16) float g_xA[B_ * D_];
__device__ __align__(16) float g_xB[B_ * D_];
// gate-interleaved repacked weights: row n <- orig row (n&3)*H + (n>>2)
__device__ __align__(16) float g_WencHH[N4H * H_];
__device__ __align__(16) float g_WencIH[N4H * D_];
__device__ __align__(16) float g_WdecIH[N4H * H_];
__device__ __align__(16) float g_WdecHH[N4H * H_];
__device__ float g_bEnc[N4H];   // b_ih + b_hh, interleaved
__device__ float g_bDec[N4H];

__device__ __forceinline__ float sigf(float x) { return 1.f / (1.f + __expf(-x)); }

// ---------------- init: zero h0/c0, load decoder input x0 = input[:, L-1, :] -------
__global__ void init_kernel(const float* __restrict__ input) {
    int idx = blockIdx.x * blockDim.x + threadIdx.x;
    if (idx < B_ * H_) { g_hA[idx] = 0.f; g_c[idx] = 0.f; }
    if (idx < B_ * D_) {
        int b = idx >> 2, d = idx & 3;
        g_xA[idx] = input[b * (L_ * D_) + (L_ - 1) * D_ + d];
    }
}

// ---------------- repack weights gate-interleaved, pre-sum biases ------------------
__global__ void repack_kernel(const float* __restrict__ encHH, const float* __restrict__ encIH,
                              const float* __restrict__ decIH, const float* __restrict__ decHH,
                              const float* __restrict__ eb1, const float* __restrict__ eb2,
                              const float* __restrict__ db1, const float* __restrict__ db2)
{
    int n = blockIdx.x;                 // 0..2047 (new row)
    int src = (n & 3) * H_ + (n >> 2);  // original row
    for (int k = threadIdx.x; k < H_; k += blockDim.x) {
        g_WencHH[n * H_ + k] = encHH[src * H_ + k];
        g_WdecIH[n * H_ + k] = decIH[src * H_ + k];
        g_WdecHH[n * H_ + k] = decHH[src * H_ + k];
    }
    if (threadIdx.x < D_) g_WencIH[n * D_ + threadIdx.x] = encIH[src * D_ + threadIdx.x];
    if (threadIdx.x == 0) {
        g_bEnc[n] = eb1[src] + eb2[src];
        g_bDec[n] = db1[src] + db2[src];
    }
}

// ---------------- fused gates GEMM + LSTM cell -------------------------------------
// Computes gates = A0@W0^T [+ A1@W1^T] [+ Asm@Wsm^T] + bias with W row-major
// gate-interleaved (N4H x 512 repacked, ld=512; Wsm N4H x 4), then applies the
// LSTM cell in-register and writes c/h (and optionally the encoder output slot).
// Tile 128x128, 256 threads, 8x8 microtile in two 4-row/4-col groups at stride 64
// (each 4-col group = the 4 gates of one hidden unit). BK=8, double-buffered.
template<int NPASS, bool HAS_SMALL, bool WRITE_ENC>
__global__ void __launch_bounds__(256)
gates_kernel(const float* __restrict__ A0, const float* __restrict__ W0,
             const float* __restrict__ A1, const float* __restrict__ W1,
             const float* __restrict__ Asm, int ldasm, const float* __restrict__ Wsm,
             const float* __restrict__ bias,
             const float* __restrict__ c_in, float* __restrict__ c_out,
             float* __restrict__ h_out, float* __restrict__ enc_slot)
{
    __shared__ __align__(16) float As[2][8][132];
    __shared__ __align__(16) float Bs[2][8][132];
    __shared__ __align__(16) float AsS[128][4];
    __shared__ __align__(16) float WsS[128][4];

    const int tid = threadIdx.x;
    const int tx = tid & 15;            // 16 column subgroups
    const int ty = tid >> 4;            // 16 row subgroups
    const int bn = blockIdx.x * 128;
    const int bm = blockIdx.y * 128;

    const int lrow = tid >> 1;          // 0..127 (gmem tile loader row)
    const int lk4  = (tid & 1) * 4;     // which half of the 8 k's

    float acc[8][8];
    #pragma unroll
    for (int r = 0; r < 8; r++)
        #pragma unroll
        for (int c = 0; c < 8; c++) acc[r][c] = 0.f;

    // stage small K=4 operand (encoder x-term)
    if (HAS_SMALL) {
        if (tid < 128) {
            float4 v = *reinterpret_cast<const float4*>(&Asm[(bm + tid) * ldasm]);
            AsS[tid][0] = v.x; AsS[tid][1] = v.y; AsS[tid][2] = v.z; AsS[tid][3] = v.w;
        } else {
            int r = tid - 128;
            float4 v = *reinterpret_cast<const float4*>(&Wsm[(bn + r) * 4]);
            WsS[r][0] = v.x; WsS[r][1] = v.y; WsS[r][2] = v.z; WsS[r][3] = v.w;
        }
    }

    // preload chunk 0 (pass 0)
    {
        float4 av = *reinterpret_cast<const float4*>(&A0[(bm + lrow) * H_ + lk4]);
        float4 wv = *reinterpret_cast<const float4*>(&W0[(bn + lrow) * H_ + lk4]);
        As[0][lk4 + 0][lrow] = av.x; As[0][lk4 + 1][lrow] = av.y;
        As[0][lk4 + 2][lrow] = av.z; As[0][lk4 + 3][lrow] = av.w;
        Bs[0][lk4 + 0][lrow] = wv.x; Bs[0][lk4 + 1][lrow] = wv.y;
        Bs[0][lk4 + 2][lrow] = wv.z; Bs[0][lk4 + 3][lrow] = wv.w;
    }
    __syncthreads();

    const int NC = 64 * NPASS;
    int s = 0;
    #pragma unroll 1
    for (int ch = 0; ch < NC; ++ch) {
        float4 avn, wvn;
        const bool has_next = (ch + 1 < NC);
        if (has_next) {
            int cn = ch + 1;
            const float* A = (NPASS == 2 && (cn >> 6)) ? A1 : A0;
            const float* W = (NPASS == 2 && (cn >> 6)) ? W1 : W0;
            int k0 = (cn & 63) * 8;
            avn = *reinterpret_cast<const float4*>(&A[(bm + lrow) * H_ + k0 + lk4]);
            wvn = *reinterpret_cast<const float4*>(&W[(bn + lrow) * H_ + k0 + lk4]);
        }
        #pragma unroll
        for (int kk = 0; kk < 8; ++kk) {
            float4 a0 = *reinterpret_cast<const float4*>(&As[s][kk][ty * 4]);
            float4 a1 = *reinterpret_cast<const float4*>(&As[s][kk][64 + ty * 4]);
            float4 b0 = *reinterpret_cast<const float4*>(&Bs[s][kk][tx * 4]);
            float4 b1 = *reinterpret_cast<const float4*>(&Bs[s][kk][64 + tx * 4]);
            float ar[8] = {a0.x, a0.y, a0.z, a0.w, a1.x, a1.y, a1.z, a1.w};
            float br[8] = {b0.x, b0.y, b0.z, b0.w, b1.x, b1.y, b1.z, b1.w};
            #pragma unroll
            for (int r = 0; r < 8; r++)
                #pragma unroll
                for (int c = 0; c < 8; c++)
                    acc[r][c] += ar[r] * br[c];
        }
        if (has_next) {
            As[s ^ 1][lk4 + 0][lrow] = avn.x; As[s ^ 1][lk4 + 1][lrow] = avn.y;
            As[s ^ 1][lk4 + 2][lrow] = avn.z; As[s ^ 1][lk4 + 3][lrow] = avn.w;
            Bs[s ^ 1][lk4 + 0][lrow] = wvn.x; Bs[s ^ 1][lk4 + 1][lrow] = wvn.y;
            Bs[s ^ 1][lk4 + 2][lrow] = wvn.z; Bs[s ^ 1][lk4 + 3][lrow] = wvn.w;
        }
        __syncthreads();
        s ^= 1;
    }

    // small K=4 contribution
    if (HAS_SMALL) {
        #pragma unroll
        for (int rg = 0; rg < 2; rg++)
            #pragma unroll
            for (int ri = 0; ri < 4; ri++) {
                int m = rg * 64 + ty * 4 + ri;
                float a0 = AsS[m][0], a1 = AsS[m][1], a2 = AsS[m][2], a3 = AsS[m][3];
                #pragma unroll
                for (int cg = 0; cg < 2; cg++)
                    #pragma unroll
                    for (int ci = 0; ci < 4; ci++) {
                        int cc = cg * 64 + tx * 4 + ci;
                        acc[rg * 4 + ri][cg * 4 + ci] +=
                            a0 * WsS[cc][0] + a1 * WsS[cc][1] + a2 * WsS[cc][2] + a3 * WsS[cc][3];
                    }
            }
    }

    // bias
    float bias_v[8];
    #pragma unroll
    for (int cg = 0; cg < 2; cg++)
        #pragma unroll
        for (int ci = 0; ci < 4; ci++)
            bias_v[cg * 4 + ci] = bias[bn + cg * 64 + tx * 4 + ci];

    // fused LSTM cell epilogue: each 4-col group = (i,f,g,o) of one unit
    #pragma unroll
    for (int rg = 0; rg < 2; rg++) {
        #pragma unroll
        for (int ri = 0; ri < 4; ri++) {
            const int r = rg * 4 + ri;
            const int row = bm + rg * 64 + ty * 4 + ri;
            #pragma unroll
            for (int cg = 0; cg < 2; cg++) {
                float pi = acc[r][cg * 4 + 0] + bias_v[cg * 4 + 0];
                float pf = acc[r][cg * 4 + 1] + bias_v[cg * 4 + 1];
                float pg = acc[r][cg * 4 + 2] + bias_v[cg * 4 + 2];
                float po = acc[r][cg * 4 + 3] + bias_v[cg * 4 + 3];
                const int u = (bn >> 2) + cg * 16 + tx;
                float cold = c_in[row * H_ + u];
                float cn = sigf(pf) * cold + sigf(pi) * tanhf(pg);
                float hn = sigf(po) * tanhf(cn);
                c_out[row * H_ + u] = cn;
                h_out[row * H_ + u] = hn;
                if (WRITE_ENC) enc_slot[row * (L_ * H_) + u] = hn;
            }
        }
    }
}

// ---------------- comb GEMM: relu([x, attn] @ comb_W^T + comb_b) -------------------
// Tile 64x128, 256 threads, 4x8 microtile (two 4-col groups at stride 64).
__global__ void __launch_bounds__(256)
comb_kernel(const float* __restrict__ A,      // attn (1024 x 512)
            const float* __restrict__ W,      // comb_W + D (512 rows, ld=CW)
            const float* __restrict__ x,      // (1024 x 4)
            const float* __restrict__ Wsm,    // comb_W (first 4 cols, ld=CW)
            const float* __restrict__ bias,
            float* __restrict__ out)
{
    __shared__ __align__(16) float As[2][8][68];
    __shared__ __align__(16) float Bs[2][8][132];
    __shared__ __align__(16) float AsS[64][4];
    __shared__ __align__(16) float WsS[128][4];

    const int tid = threadIdx.x;
    const int tx = tid & 15;
    const int ty = tid >> 4;
    const int bn = blockIdx.x * 128;
    const int bm = blockIdx.y * 64;

    const int lrowB = tid >> 1, lk4 = (tid & 1) * 4;
    const int lrowA = tid >> 2, lk2 = (tid & 3) * 2;

    float acc[4][8];
    #pragma unroll
    for (int r = 0; r < 4; r++)
        #pragma unroll
        for (int c = 0; c < 8; c++) acc[r][c] = 0.f;

    if (tid < 64) {
        float4 v = *reinterpret_cast<const float4*>(&x[(bm + tid) * 4]);
        AsS[tid][0] = v.x; AsS[tid][1] = v.y; AsS[tid][2] = v.z; AsS[tid][3] = v.w;
    } else if (tid < 192) {
        int r = tid - 64;
        float4 v = *reinterpret_cast<const float4*>(&Wsm[(bn + r) * CW]);
        WsS[r][0] = v.x; WsS[r][1] = v.y; WsS[r][2] = v.z; WsS[r][3] = v.w;
    }

    {
        float2 av = *reinterpret_cast<const float2*>(&A[(bm + lrowA) * H_ + lk2]);
        float4 wv = *reinterpret_cast<const float4*>(&W[(bn + lrowB) * CW + lk4]);
        As[0][lk2 + 0][lrowA] = av.x; As[0][lk2 + 1][lrowA] = av.y;
        Bs[0][lk4 + 0][lrowB] = wv.x; Bs[0][lk4 + 1][lrowB] = wv.y;
        Bs[0][lk4 + 2][lrowB] = wv.z; Bs[0][lk4 + 3][lrowB] = wv.w;
    }
    __syncthreads();

    int s = 0;
    #pragma unroll 1
    for (int ch = 0; ch < 64; ++ch) {
        float2 avn; float4 wvn;
        const bool has_next = (ch + 1 < 64);
        if (has_next) {
            int k0 = (ch + 1) * 8;
            avn = *reinterpret_cast<const float2*>(&A[(bm + lrowA) * H_ + k0 + lk2]);
            wvn = *reinterpret_cast<const float4*>(&W[(bn + lrowB) * CW + k0 + lk4]);
        }
        #pragma unroll
        for (int kk = 0; kk < 8; ++kk) {
            float4 a = *reinterpret_cast<const float4*>(&As[s][kk][ty * 4]);
            float4 b0 = *reinterpret_cast<const float4*>(&Bs[s][kk][tx * 4]);
            float4 b1 = *reinterpret_cast<const float4*>(&Bs[s][kk][64 + tx * 4]);
            float ar[4] = {a.x, a.y, a.z, a.w};
            float br[8] = {b0.x, b0.y, b0.z, b0.w, b1.x, b1.y, b1.z, b1.w};
            #pragma unroll
            for (int r = 0; r < 4; r++)
                #pragma unroll
                for (int c = 0; c < 8; c++)
                    acc[r][c] += ar[r] * br[c];
        }
        if (has_next) {
            As[s ^ 1][lk2 + 0][lrowA] = avn.x; As[s ^ 1][lk2 + 1][lrowA] = avn.y;
            Bs[s ^ 1][lk4 + 0][lrowB] = wvn.x; Bs[s ^ 1][lk4 + 1][lrowB] = wvn.y;
            Bs[s ^ 1][lk4 + 2][lrowB] = wvn.z; Bs[s ^ 1][lk4 + 3][lrowB] = wvn.w;
        }
        __syncthreads();
        s ^= 1;
    }

    #pragma unroll
    for (int ri = 0; ri < 4; ri++) {
        const int row = bm + ty * 4 + ri;
        float a0 = AsS[ty * 4 + ri][0], a1 = AsS[ty * 4 + ri][1];
        float a2 = AsS[ty * 4 + ri][2], a3 = AsS[ty * 4 + ri][3];
        #pragma unroll
        for (int cg = 0; cg < 2; cg++) {
            float v[4];
            #pragma unroll
            for (int ci = 0; ci < 4; ci++) {
                int cc = cg * 64 + tx * 4 + ci;
                float t = acc[ri][cg * 4 + ci]
                        + a0 * WsS[cc][0] + a1 * WsS[cc][1] + a2 * WsS[cc][2] + a3 * WsS[cc][3]
                        + bias[bn + cc];
                v[ci] = fmaxf(t, 0.f);
            }
            *reinterpret_cast<float4*>(&out[row * H_ + bn + cg * 64 + tx * 4]) =
                make_float4(v[0], v[1], v[2], v[3]);
        }
    }
}

// ---------------- attention: logits -> softmax -> weighted sum of enc outputs -----
// Replicates h_r = h.reshape(H,-1).T : h_r[b,k] = h[2k + (b>=512), b & 511]
__global__ void __launch_bounds__(256)
attn_kernel(const float* __restrict__ x, const float* __restrict__ h,
            const float* __restrict__ attn_W, const float* __restrict__ attn_b,
            const float* __restrict__ enc, float* __restrict__ out)
{
    __shared__ float v[H_ + D_];
    __shared__ float wts[64];
    const int b = blockIdx.x;
    const int tid = threadIdx.x;

    if (tid < D_) v[tid] = x[b * D_ + tid];
    {
        int brow = b >> 9, bcol = b & 511;
        for (int k = tid; k < H_; k += 256)
            v[D_ + k] = h[(2 * k + brow) * H_ + bcol];
    }
    __syncthreads();

    const int warp = tid >> 5, lane = tid & 31;
    for (int l = warp; l < L_; l += 8) {
        const float* wrow = attn_W + l * (H_ + D_);
        float s = 0.f;
        for (int k = lane; k < H_ + D_; k += 32) s += v[k] * wrow[k];
        #pragma unroll
        for (int off = 16; off; off >>= 1) s += __shfl_xor_sync(0xffffffffu, s, off);
        if (lane == 0) wts[l] = s + attn_b[l];
    }
    __syncthreads();

    if (tid < 32) {
        float v1 = (tid < L_) ? wts[tid] : -1e30f;
        float v2 = (tid + 32 < L_) ? wts[tid + 32] : -1e30f;
        float m = fmaxf(v1, v2);
        #pragma unroll
        for (int off = 16; off; off >>= 1) m = fmaxf(m, __shfl_xor_sync(0xffffffffu, m, off));
        float e1 = (tid < L_) ? __expf(v1 - m) : 0.f;
        float e2 = (tid + 32 < L_) ? __expf(v2 - m) : 0.f;
        float s = e1 + e2;
        #pragma unroll
        for (int off = 16; off; off >>= 1) s += __shfl_xor_sync(0xffffffffu, s, off);
        float inv = 1.f / s;
        if (tid < L_) wts[tid] = e1 * inv;
        if (tid + 32 < L_) wts[tid + 32] = e2 * inv;
    }
    __syncthreads();

    const float* e = enc + b * (L_ * H_);
    for (int j = tid; j < H_; j += 256) {
        float s = 0.f;
        #pragma unroll
        for (int l = 0; l < L_; l++) s += wts[l] * e[l * H_ + j];
        out[b * H_ + j] = s;
    }
}

// ---------------- pred: pred = h @ out_W^T + out_b ; also next decoder input -------
__global__ void pred_kernel(const float* __restrict__ h, const float* __restrict__ out_W,
                            const float* __restrict__ out_b, float* __restrict__ out,
                            int t, float* __restrict__ x_next)
{
    const int b = blockIdx.x;
    const int warp = threadIdx.x >> 5, lane = threadIdx.x & 31;   // 4 warps = 4 outputs
    const float* hr = h + b * H_;
    const float* w = out_W + warp * H_;
    float s = 0.f;
    #pragma unroll
    for (int k = lane; k < H_; k += 32) s += hr[k] * w[k];
    #pragma unroll
    for (int off = 16; off; off >>= 1) s += __shfl_xor_sync(0xffffffffu, s, off);
    if (lane == 0) {
        float p = s + out_b[warp];
        out[(b * T_ + t) * D_ + warp] = p;
        x_next[b * D_ + warp] = p;
    }
}

// ------------------------------------- launch -------------------------------------
extern "C" void kernel_launch(void* const* d_in, const int* in_sizes, int n_in,
                              void* d_out, int out_size)
{
    int base = (n_in >= 16 && in_sizes[1] == 1) ? 2 : 1;

    const float* input    = (const float*)d_in[0];
    const float* enc_W_ih = (const float*)d_in[base + 0];
    const float* enc_W_hh = (const float*)d_in[base + 1];
    const float* enc_b_ih = (const float*)d_in[base + 2];
    const float* enc_b_hh = (const float*)d_in[base + 3];
    const float* attn_W   = (const float*)d_in[base + 4];
    const float* attn_b   = (const float*)d_in[base + 5];
    const float* comb_W   = (const float*)d_in[base + 6];
    const float* comb_b   = (const float*)d_in[base + 7];
    const float* dec_W_ih = (const float*)d_in[base + 8];
    const float* dec_W_hh = (const float*)d_in[base + 9];
    const float* dec_b_ih = (const float*)d_in[base + 10];
    const float* dec_b_hh = (const float*)d_in[base + 11];
    const float* out_W    = (const float*)d_in[base + 12];
    const float* out_b    = (const float*)d_in[base + 13];
    float* outp = (float*)d_out;

    float *hA, *hB, *c, *enc, *attn, *comb, *xA, *xB;
    float *WencHH, *WencIH, *WdecIH, *WdecHH, *bEnc, *bDec;
    cudaGetSymbolAddress((void**)&hA, g_hA);
    cudaGetSymbolAddress((void**)&hB, g_hB);
    cudaGetSymbolAddress((void**)&c, g_c);
    cudaGetSymbolAddress((void**)&enc, g_enc);
    cudaGetSymbolAddress((void**)&attn, g_attn);
    cudaGetSymbolAddress((void**)&comb, g_comb);
    cudaGetSymbolAddress((void**)&xA, g_xA);
    cudaGetSymbolAddress((void**)&xB, g_xB);
    cudaGetSymbolAddress((void**)&WencHH, g_WencHH);
    cudaGetSymbolAddress((void**)&WencIH, g_WencIH);
    cudaGetSymbolAddress((void**)&WdecIH, g_WdecIH);
    cudaGetSymbolAddress((void**)&WdecHH, g_WdecHH);
    cudaGetSymbolAddress((void**)&bEnc, g_bEnc);
    cudaGetSymbolAddress((void**)&bDec, g_bDec);

    init_kernel<<<(B_ * H_ + 255) / 256, 256>>>(input);
    repack_kernel<<<N4H, 128>>>(enc_W_hh, enc_W_ih, dec_W_ih, dec_W_hh,
                                enc_b_ih, enc_b_hh, dec_b_ih, dec_b_hh);

    const dim3 grid_gates(N4H / 128, B_ / 128);
    const dim3 grid_comb(H_ / 128, B_ / 64);

    // ---------------- encoder ----------------
    float* h_in = hA;
    float* h_out = hB;
    for (int t = 0; t < L_; t++) {
        gates_kernel<1, true, true><<<grid_gates, 256>>>(
            h_in, WencHH, nullptr, nullptr,
            input + t * D_, L_ * D_, WencIH,
            bEnc, c, c, h_out, enc + t * H_);
        float* tmp = h_in; h_in = h_out; h_out = tmp;
    }

    // ---------------- decoder ----------------
    float* x_in = xA;
    float* x_out = xB;
    for (int t = 0; t < T_; t++) {
        attn_kernel<<<B_, 256>>>(x_in, h_in, attn_W, attn_b, enc, attn);
        comb_kernel<<<grid_comb, 256>>>(attn, comb_W + D_, x_in, comb_W, comb_b, comb);
        gates_kernel<2, false, false><<<grid_gates, 256>>>(
            comb, WdecIH, h_in, WdecHH,
            nullptr, 0, nullptr,
            bDec, c, c, h_out, nullptr);
        pred_kernel<<<B_, 128>>>(h_out, out_W, out_b, outp, t, x_out);
        float* tmp = h_in; h_in = h_out; h_out = tmp;
        float* tx = x_in; x_in = x_out; x_out = tx;
    }
}

// round 10
// speedup vs baseline: 1.1612x; 1.1612x over previous
#include <cuda_runtime.h>
#include <cuda_bf16.h>
#include <math.h>
#include <stdint.h>

#define B_  1024
#define L_  50
#define D_  4
#define H_  512
#define T_  30
#define N4H 2048
#define CW  516

typedef __nv_bfloat16 bf16;

// ===================== base-ISA PTX helpers (sm_80+ features only) =====================
__device__ __forceinline__ uint32_t smem_u32(const void* p) {
    uint32_t a;
    asm("{ .reg .u64 t; cvta.to.shared.u64 t, %1; cvt.u32.u64 %0, t; }" : "=r"(a) : "l"(p));
    return a;
}
__device__ __forceinline__ void mma16816(float* d, const uint32_t* a, const uint32_t* b) {
    asm volatile(
        "mma.sync.aligned.m16n8k16.row.col.f32.bf16.bf16.f32 "
        "{%0,%1,%2,%3}, {%4,%5,%6,%7}, {%8,%9}, {%0,%1,%2,%3};"
        : "+f"(d[0]), "+f"(d[1]), "+f"(d[2]), "+f"(d[3])
        : "r"(a[0]), "r"(a[1]), "r"(a[2]), "r"(a[3]), "r"(b[0]), "r"(b[1]));
}
__device__ __forceinline__ void ldsm4(uint32_t* r, uint32_t addr) {
    asm volatile("ldmatrix.sync.aligned.m8n8.x4.shared.b16 {%0,%1,%2,%3}, [%4];"
        : "=r"(r[0]), "=r"(r[1]), "=r"(r[2]), "=r"(r[3]) : "r"(addr));
}
#define CP_ASYNC16(sa, gp) \
    asm volatile("cp.async.ca.shared.global [%0], [%1], 16;" :: "r"(sa), "l"(gp) : "memory")
#define CP_COMMIT() asm volatile("cp.async.commit_group;" ::: "memory")
#define CP_WAIT0()  asm volatile("cp.async.wait_group 0;" ::: "memory")
#define CP_WAIT1()  asm volatile("cp.async.wait_group 1;" ::: "memory")

__device__ __forceinline__ float sigf(float x) { return 1.f / (1.f + __expf(-x)); }
__device__ __forceinline__ void bsplit(float v, bf16& hi, bf16& lo) {
    hi = __float2bfloat16(v);
    lo = __float2bfloat16(v - __bfloat162float(hi));
}

// ============================ persistent device state ============================
__device__ __align__(16) float g_hA[B_ * H_];
__device__ __align__(16) float g_hB[B_ * H_];
__device__ __align__(16) bf16  g_hAh[B_ * H_];
__device__ __align__(16) bf16  g_hAl[B_ * H_];
__device__ __align__(16) bf16  g_hBh[B_ * H_];
__device__ __align__(16) bf16  g_hBl[B_ * H_];
__device__ __align__(16) float g_c[B_ * H_];
__device__ __align__(16) float g_enc[B_ * L_ * H_];
__device__ __align__(16) bf16  g_attnH[B_ * H_];
__device__ __align__(16) bf16  g_attnL[B_ * H_];
__device__ __align__(16) bf16  g_combH[B_ * H_];
__device__ __align__(16) bf16  g_combL[B_ * H_];
__device__ __align__(16) float g_xA[B_ * D_];
__device__ __align__(16) float g_xB[B_ * D_];
// gate-permuted weights for fused LSTM epilogue:
// new col n: chunk=n>>4, w=n&15, gate=((w>>3)<<1)|(w&1), unit=chunk*4+((w>>1)&3)
__device__ __align__(16) bf16  g_WencHHh[N4H * H_];
__device__ __align__(16) bf16  g_WencHHl[N4H * H_];
__device__ __align__(16) bf16  g_WdecIHh[N4H * H_];
__device__ __align__(16) bf16  g_WdecIHl[N4H * H_];
__device__ __align__(16) bf16  g_WdecHHh[N4H * H_];
__device__ __align__(16) bf16  g_WdecHHl[N4H * H_];
__device__ __align__(16) float g_WencIH[N4H * D_];
__device__ __align__(16) bf16  g_combWh[H_ * H_];
__device__ __align__(16) bf16  g_combWl[H_ * H_];
__device__ __align__(16) float g_combWsm[H_ * D_];
__device__ float g_bEnc[N4H];
__device__ float g_bDec[N4H];

// ============================ init / repack ============================
__global__ void init_kernel(const float* __restrict__ input) {
    int idx = blockIdx.x * blockDim.x + threadIdx.x;
    if (idx < B_ * H_) {
        g_hA[idx] = 0.f; g_c[idx] = 0.f;
        g_hAh[idx] = __float2bfloat16(0.f); g_hAl[idx] = __float2bfloat16(0.f);
    }
    if (idx < B_ * D_) {
        int b = idx >> 2, d = idx & 3;
        g_xA[idx] = input[b * (L_ * D_) + (L_ - 1) * D_ + d];
    }
}

__global__ void repack_kernel(const float* __restrict__ encHH, const float* __restrict__ encIH,
                              const float* __restrict__ decIH, const float* __restrict__ decHH,
                              const float* __restrict__ combW,
                              const float* __restrict__ eb1, const float* __restrict__ eb2,
                              const float* __restrict__ db1, const float* __restrict__ db2)
{
    int n = blockIdx.x;                          // new row index 0..2047
    int w = n & 15, chunk = n >> 4;
    int gate = ((w >> 3) << 1) | (w & 1);
    int u = chunk * 4 + ((w >> 1) & 3);
    int src = gate * H_ + u;
    for (int k = threadIdx.x; k < H_; k += blockDim.x) {
        bf16 hi, lo;
        bsplit(encHH[src * H_ + k], hi, lo);
        g_WencHHh[n * H_ + k] = hi; g_WencHHl[n * H_ + k] = lo;
        bsplit(decIH[src * H_ + k], hi, lo);
        g_WdecIHh[n * H_ + k] = hi; g_WdecIHl[n * H_ + k] = lo;
        bsplit(decHH[src * H_ + k], hi, lo);
        g_WdecHHh[n * H_ + k] = hi; g_WdecHHl[n * H_ + k] = lo;
        if (n < H_) {
            bsplit(combW[n * CW + D_ + k], hi, lo);      // natural order for comb
            g_combWh[n * H_ + k] = hi; g_combWl[n * H_ + k] = lo;
        }
    }
    if (threadIdx.x < D_) {
        g_WencIH[n * D_ + threadIdx.x] = encIH[src * D_ + threadIdx.x];
        if (n < H_) g_combWsm[n * D_ + threadIdx.x] = combW[n * CW + threadIdx.x];
    }
    if (threadIdx.x == 0) {
        g_bEnc[n] = eb1[src] + eb2[src];
        g_bDec[n] = db1[src] + db2[src];
    }
}

// ============================ HMMA GEMM (+fused epilogue) ============================
// C[128x128] = A(hi/lo bf16, MxK row-major) @ W(hi/lo bf16, NxK row-major)^T via
// 3x mma.sync.m16n8k16 per k16 (hi*hi + hi*lo + lo*hi), fp32 accum in regs.
// 8 warps, warp tile 32m x 64n. BK=32, cp.async double buffer, 80B-padded rows.
// Epilogue: +bias (+K=4 fp32 rank-4 term), LSTM cell (gate-permuted cols) or relu.

#define TILE_B  (128 * 80)              // one 128x32 bf16 tile, 80B row stride
#define STAGE_B (4 * TILE_B)            // Ah, Al, Bh, Bl
#define SM_BIAS (2 * STAGE_B)           // 81920: 128 floats
#define SM_XS   (SM_BIAS + 512)         // 128 x 4 floats
#define SM_WS   (SM_XS + 2048)          // 128 x 4 floats
#define SMEM_TOTAL (SM_WS + 2048)       // 86528 bytes

template<int NPASS, bool HAS_SMALL, bool LSTM_EPI, bool WRITE_ENC>
__global__ void __launch_bounds__(256, 1)
mma_kernel(const bf16* __restrict__ A0h, const bf16* __restrict__ A0l,
           const bf16* __restrict__ B0h, const bf16* __restrict__ B0l,
           const bf16* __restrict__ A1h, const bf16* __restrict__ A1l,
           const bf16* __restrict__ B1h, const bf16* __restrict__ B1l,
           const float* __restrict__ Asm, int ldasm, const float* __restrict__ Wsm,
           const float* __restrict__ bias,
           const float* __restrict__ c_in, float* __restrict__ c_out,
           float* __restrict__ h_out, bf16* __restrict__ hh_out, bf16* __restrict__ hl_out,
           float* __restrict__ enc_slot)
{
    extern __shared__ char smem[];
    const uint32_t sb = smem_u32(smem);
    const int tid = threadIdx.x;
    const int wid = tid >> 5, lane = tid & 31;
    const int warp_m = wid & 3, warp_n = wid >> 2;
    const int lane8 = lane & 7, sel = lane >> 3;
    const int gID = lane >> 2, tig = lane & 3;
    const int bn = blockIdx.x * 128;
    const int bm = blockIdx.y * 128;

    float* sbias = (float*)(smem + SM_BIAS);
    float* xs    = (float*)(smem + SM_XS);
    float* ws    = (float*)(smem + SM_WS);

    if (tid < 128) sbias[tid] = bias[bn + tid];
    if (HAS_SMALL) {
        if (tid < 128) {
            const float* xr = Asm + (size_t)(bm + tid) * ldasm;
            xs[tid * 4 + 0] = xr[0]; xs[tid * 4 + 1] = xr[1];
            xs[tid * 4 + 2] = xr[2]; xs[tid * 4 + 3] = xr[3];
        } else {
            int r = tid - 128;
            float4 v = *reinterpret_cast<const float4*>(&Wsm[(bn + r) * 4]);
            ws[r * 4 + 0] = v.x; ws[r * 4 + 1] = v.y; ws[r * 4 + 2] = v.z; ws[r * 4 + 3] = v.w;
        }
    }

    float acc[2][8][4];
    #pragma unroll
    for (int mt = 0; mt < 2; mt++)
        #pragma unroll
        for (int nt = 0; nt < 8; nt++)
            #pragma unroll
            for (int c = 0; c < 4; c++) acc[mt][nt][c] = 0.f;

    const int NS = NPASS * 16;

    auto load_stage = [&](int buf, int s) {
        const bool p1 = (NPASS == 2) && (s >= 16);
        const bf16* Ah = p1 ? A1h : A0h;
        const bf16* Al = p1 ? A1l : A0l;
        const bf16* Bh = p1 ? B1h : B0h;
        const bf16* Bl = p1 ? B1l : B0l;
        const int k0 = (s & 15) * 32;
        const uint32_t tb = sb + buf * STAGE_B;
        #pragma unroll
        for (int j = 0; j < 8; j++) {
            const int tile = j >> 1;
            const int lin = ((j & 1) << 8) + tid;      // 0..511
            const int row = lin >> 2, seg = lin & 3;
            const bf16* g = (tile == 0) ? Ah : (tile == 1) ? Al : (tile == 2) ? Bh : Bl;
            const int grow = ((tile < 2) ? bm : bn) + row;
            const bf16* gp = g + (size_t)grow * H_ + k0 + seg * 8;
            const uint32_t sa = tb + tile * TILE_B + row * 80 + seg * 16;
            CP_ASYNC16(sa, gp);
        }
        CP_COMMIT();
    };

    auto compute = [&](int buf) {
        const uint32_t tb = sb + buf * STAGE_B;
        #pragma unroll
        for (int kq = 0; kq < 2; kq++) {
            const int kk = kq * 16;
            uint32_t ah[2][4], al[2][4];
            #pragma unroll
            for (int mt = 0; mt < 2; mt++) {
                uint32_t ra = tb + (uint32_t)((warp_m * 32 + mt * 16 + ((sel & 1) << 3) + lane8) * 80
                                              + (kk + ((sel >> 1) << 3)) * 2);
                ldsm4(ah[mt], ra);
                ldsm4(al[mt], ra + TILE_B);
            }
            uint32_t bh[4][4], bl[4][4];
            #pragma unroll
            for (int p = 0; p < 4; p++) {
                uint32_t rb = tb + 2 * TILE_B
                            + (uint32_t)((warp_n * 64 + (2 * p + (sel >> 1)) * 8 + lane8) * 80
                                         + (kk + ((sel & 1) << 3)) * 2);
                ldsm4(bh[p], rb);
                ldsm4(bl[p], rb + TILE_B);
            }
            #pragma unroll
            for (int mt = 0; mt < 2; mt++)
                #pragma unroll
                for (int p = 0; p < 4; p++) {
                    mma16816(acc[mt][2 * p],     ah[mt], bh[p]);
                    mma16816(acc[mt][2 * p + 1], ah[mt], bh[p] + 2);
                    mma16816(acc[mt][2 * p],     ah[mt], bl[p]);
                    mma16816(acc[mt][2 * p + 1], ah[mt], bl[p] + 2);
                    mma16816(acc[mt][2 * p],     al[mt], bh[p]);
                    mma16816(acc[mt][2 * p + 1], al[mt], bh[p] + 2);
                }
        }
    };

    load_stage(0, 0);
    #pragma unroll 1
    for (int s = 0; s < NS; s++) {
        if (s + 1 < NS) { load_stage((s + 1) & 1, s + 1); CP_WAIT1(); }
        else            { CP_WAIT0(); }
        __syncthreads();
        compute(s & 1);
        __syncthreads();
    }

    // -------------------- epilogue --------------------
    if (LSTM_EPI) {
        #pragma unroll
        for (int mt = 0; mt < 2; mt++) {
            #pragma unroll
            for (int rh = 0; rh < 2; rh++) {           // C-fragment row half (+0 / +8)
                const int rl = warp_m * 32 + mt * 16 + gID + rh * 8;
                const int grow = bm + rl;
                const int ci = rh * 2;
                float x0 = 0.f, x1 = 0.f, x2 = 0.f, x3 = 0.f;
                if (HAS_SMALL) {
                    const float* xr = xs + rl * 4;
                    x0 = xr[0]; x1 = xr[1]; x2 = xr[2]; x3 = xr[3];
                }
                #pragma unroll
                for (int k = 0; k < 4; k++) {
                    const int ni = warp_n * 64 + k * 16 + 2 * tig;   // local col of gate i
                    float pi = acc[mt][2 * k][ci]     + sbias[ni];
                    float pf = acc[mt][2 * k][ci + 1] + sbias[ni + 1];
                    float pg = acc[mt][2 * k + 1][ci]     + sbias[ni + 8];
                    float po = acc[mt][2 * k + 1][ci + 1] + sbias[ni + 9];
                    if (HAS_SMALL) {
                        const float* wi = ws + ni * 4;
                        const float* wf = ws + (ni + 1) * 4;
                        const float* wg = ws + (ni + 8) * 4;
                        const float* wo = ws + (ni + 9) * 4;
                        pi += x0 * wi[0] + x1 * wi[1] + x2 * wi[2] + x3 * wi[3];
                        pf += x0 * wf[0] + x1 * wf[1] + x2 * wf[2] + x3 * wf[3];
                        pg += x0 * wg[0] + x1 * wg[1] + x2 * wg[2] + x3 * wg[3];
                        po += x0 * wo[0] + x1 * wo[1] + x2 * wo[2] + x3 * wo[3];
                    }
                    const int u = (bn >> 2) + warp_n * 16 + k * 4 + tig;
                    const int idx = grow * H_ + u;
                    float cold = c_in[idx];
                    float cn = sigf(pf) * cold + sigf(pi) * tanhf(pg);
                    float hn = sigf(po) * tanhf(cn);
                    c_out[idx] = cn;
                    h_out[idx] = hn;
                    bf16 hh, hl; bsplit(hn, hh, hl);
                    hh_out[idx] = hh; hl_out[idx] = hl;
                    if (WRITE_ENC) enc_slot[grow * (L_ * H_) + u] = hn;
                }
            }
        }
    } else {
        #pragma unroll
        for (int mt = 0; mt < 2; mt++) {
            #pragma unroll
            for (int c = 0; c < 4; c++) {
                const int rl = warp_m * 32 + mt * 16 + gID + (c >> 1) * 8;
                const int grow = bm + rl;
                float x0 = 0.f, x1 = 0.f, x2 = 0.f, x3 = 0.f;
                if (HAS_SMALL) {
                    const float* xr = xs + rl * 4;
                    x0 = xr[0]; x1 = xr[1]; x2 = xr[2]; x3 = xr[3];
                }
                #pragma unroll
                for (int nt = 0; nt < 8; nt++) {
                    const int nl = warp_n * 64 + nt * 8 + 2 * tig + (c & 1);
                    float v = acc[mt][nt][c] + sbias[nl];
                    if (HAS_SMALL) {
                        const float* w = ws + nl * 4;
                        v += x0 * w[0] + x1 * w[1] + x2 * w[2] + x3 * w[3];
                    }
                    v = fmaxf(v, 0.f);
                    const int idx = grow * H_ + bn + nl;
                    bf16 hh, hl; bsplit(v, hh, hl);
                    hh_out[idx] = hh; hl_out[idx] = hl;
                }
            }
        }
    }
}

// ============================ attention (fp32) ============================
// h_r[b,k] = h[2k + (b>=512), b & 511]  (reference's reshape/transpose quirk)
__global__ void __launch_bounds__(256)
attn_kernel(const float* __restrict__ x, const float* __restrict__ h,
            const float* __restrict__ attn_W, const float* __restrict__ attn_b,
            const float* __restrict__ enc, bf16* __restrict__ outH, bf16* __restrict__ outL)
{
    __shared__ float v[H_ + D_];
    __shared__ float wts[64];
    const int b = blockIdx.x;
    const int tid = threadIdx.x;

    if (tid < D_) v[tid] = x[b * D_ + tid];
    {
        int brow = b >> 9, bcol = b & 511;
        for (int k = tid; k < H_; k += 256)
            v[D_ + k] = h[(2 * k + brow) * H_ + bcol];
    }
    __syncthreads();

    const int warp = tid >> 5, lane = tid & 31;
    for (int l = warp; l < L_; l += 8) {
        const float* wrow = attn_W + l * (H_ + D_);
        float s = 0.f;
        for (int k = lane; k < H_ + D_; k += 32) s += v[k] * wrow[k];
        #pragma unroll
        for (int off = 16; off; off >>= 1) s += __shfl_xor_sync(0xffffffffu, s, off);
        if (lane == 0) wts[l] = s + attn_b[l];
    }
    __syncthreads();

    if (tid < 32) {
        float v1 = (tid < L_) ? wts[tid] : -1e30f;
        float v2 = (tid + 32 < L_) ? wts[tid + 32] : -1e30f;
        float m = fmaxf(v1, v2);
        #pragma unroll
        for (int off = 16; off; off >>= 1) m = fmaxf(m, __shfl_xor_sync(0xffffffffu, m, off));
        float e1 = (tid < L_) ? __expf(v1 - m) : 0.f;
        float e2 = (tid + 32 < L_) ? __expf(v2 - m) : 0.f;
        float s = e1 + e2;
        #pragma unroll
        for (int off = 16; off; off >>= 1) s += __shfl_xor_sync(0xffffffffu, s, off);
        float inv = 1.f / s;
        if (tid < L_) wts[tid] = e1 * inv;
        if (tid + 32 < L_) wts[tid + 32] = e2 * inv;
    }
    __syncthreads();

    const float* e = enc + (size_t)b * (L_ * H_);
    for (int j = tid; j < H_; j += 256) {
        float s = 0.f;
        #pragma unroll
        for (int l = 0; l < L_; l++) s += wts[l] * e[l * H_ + j];
        bf16 hi, lo; bsplit(s, hi, lo);
        outH[b * H_ + j] = hi; outL[b * H_ + j] = lo;
    }
}

// ============================ pred ============================
__global__ void pred_kernel(const float* __restrict__ h, const float* __restrict__ out_W,
                            const float* __restrict__ out_b, float* __restrict__ out,
                            int t, float* __restrict__ x_next)
{
    const int b = blockIdx.x;
    const int warp = threadIdx.x >> 5, lane = threadIdx.x & 31;
    const float* hr = h + b * H_;
    const float* w = out_W + warp * H_;
    float s = 0.f;
    #pragma unroll
    for (int k = lane; k < H_; k += 32) s += hr[k] * w[k];
    #pragma unroll
    for (int off = 16; off; off >>= 1) s += __shfl_xor_sync(0xffffffffu, s, off);
    if (lane == 0) {
        float p = s + out_b[warp];
        out[(b * T_ + t) * D_ + warp] = p;
        x_next[b * D_ + warp] = p;
    }
}

// ============================ launch ============================
extern "C" void kernel_launch(void* const* d_in, const int* in_sizes, int n_in,
                              void* d_out, int out_size)
{
    int base = (n_in >= 16 && in_sizes[1] == 1) ? 2 : 1;

    const float* input    = (const float*)d_in[0];
    const float* enc_W_ih = (const float*)d_in[base + 0];
    const float* enc_W_hh = (const float*)d_in[base + 1];
    const float* enc_b_ih = (const float*)d_in[base + 2];
    const float* enc_b_hh = (const float*)d_in[base + 3];
    const float* attn_W   = (const float*)d_in[base + 4];
    const float* attn_b   = (const float*)d_in[base + 5];
    const float* comb_W   = (const float*)d_in[base + 6];
    const float* comb_b   = (const float*)d_in[base + 7];
    const float* dec_W_ih = (const float*)d_in[base + 8];
    const float* dec_W_hh = (const float*)d_in[base + 9];
    const float* dec_b_ih = (const float*)d_in[base + 10];
    const float* dec_b_hh = (const float*)d_in[base + 11];
    const float* out_W    = (const float*)d_in[base + 12];
    const float* out_b    = (const float*)d_in[base + 13];
    float* outp = (float*)d_out;

    float *hA, *hB, *c, *enc, *xA, *xB, *WencIH, *combWsm, *bEnc, *bDec;
    bf16 *hAh, *hAl, *hBh, *hBl, *attnH, *attnL, *combH, *combL;
    bf16 *WencHHh, *WencHHl, *WdecIHh, *WdecIHl, *WdecHHh, *WdecHHl, *combWh, *combWl;
    cudaGetSymbolAddress((void**)&hA, g_hA);
    cudaGetSymbolAddress((void**)&hB, g_hB);
    cudaGetSymbolAddress((void**)&hAh, g_hAh);
    cudaGetSymbolAddress((void**)&hAl, g_hAl);
    cudaGetSymbolAddress((void**)&hBh, g_hBh);
    cudaGetSymbolAddress((void**)&hBl, g_hBl);
    cudaGetSymbolAddress((void**)&c, g_c);
    cudaGetSymbolAddress((void**)&enc, g_enc);
    cudaGetSymbolAddress((void**)&attnH, g_attnH);
    cudaGetSymbolAddress((void**)&attnL, g_attnL);
    cudaGetSymbolAddress((void**)&combH, g_combH);
    cudaGetSymbolAddress((void**)&combL, g_combL);
    cudaGetSymbolAddress((void**)&xA, g_xA);
    cudaGetSymbolAddress((void**)&xB, g_xB);
    cudaGetSymbolAddress((void**)&WencHHh, g_WencHHh);
    cudaGetSymbolAddress((void**)&WencHHl, g_WencHHl);
    cudaGetSymbolAddress((void**)&WdecIHh, g_WdecIHh);
    cudaGetSymbolAddress((void**)&WdecIHl, g_WdecIHl);
    cudaGetSymbolAddress((void**)&WdecHHh, g_WdecHHh);
    cudaGetSymbolAddress((void**)&WdecHHl, g_WdecHHl);
    cudaGetSymbolAddress((void**)&WencIH, g_WencIH);
    cudaGetSymbolAddress((void**)&combWh, g_combWh);
    cudaGetSymbolAddress((void**)&combWl, g_combWl);
    cudaGetSymbolAddress((void**)&combWsm, g_combWsm);
    cudaGetSymbolAddress((void**)&bEnc, g_bEnc);
    cudaGetSymbolAddress((void**)&bDec, g_bDec);

    cudaFuncSetAttribute(mma_kernel<1, true, true, true>,
                         cudaFuncAttributeMaxDynamicSharedMemorySize, SMEM_TOTAL);
    cudaFuncSetAttribute(mma_kernel<1, true, false, false>,
                         cudaFuncAttributeMaxDynamicSharedMemorySize, SMEM_TOTAL);
    cudaFuncSetAttribute(mma_kernel<2, false, true, false>,
                         cudaFuncAttributeMaxDynamicSharedMemorySize, SMEM_TOTAL);

    init_kernel<<<(B_ * H_ + 255) / 256, 256>>>(input);
    repack_kernel<<<N4H, 256>>>(enc_W_hh, enc_W_ih, dec_W_ih, dec_W_hh, comb_W,
                                enc_b_ih, enc_b_hh, dec_b_ih, dec_b_hh);

    const dim3 grid_gates(N4H / 128, B_ / 128);   // 16 x 8
    const dim3 grid_comb(H_ / 128, B_ / 128);     // 4 x 8

    // ---------------- encoder ----------------
    float *h_in = hA, *h_out = hB;
    bf16 *hih = hAh, *hil = hAl, *hoh = hBh, *hol = hBl;
    for (int t = 0; t < L_; t++) {
        mma_kernel<1, true, true, true><<<grid_gates, 256, SMEM_TOTAL>>>(
            hih, hil, WencHHh, WencHHl,
            nullptr, nullptr, nullptr, nullptr,
            input + t * D_, L_ * D_, WencIH,
            bEnc, c, c, h_out, hoh, hol, enc + t * H_);
        { float* tp = h_in; h_in = h_out; h_out = tp; }
        { bf16* tp = hih; hih = hoh; hoh = tp; tp = hil; hil = hol; hol = tp; }
    }

    // ---------------- decoder ----------------
    float *x_in = xA, *x_out = xB;
    for (int t = 0; t < T_; t++) {
        attn_kernel<<<B_, 256>>>(x_in, h_in, attn_W, attn_b, enc, attnH, attnL);
        mma_kernel<1, true, false, false><<<grid_comb, 256, SMEM_TOTAL>>>(
            attnH, attnL, combWh, combWl,
            nullptr, nullptr, nullptr, nullptr,
            x_in, D_, combWsm,
            comb_b, nullptr, nullptr, nullptr, combH, combL, nullptr);
        mma_kernel<2, false, true, false><<<grid_gates, 256, SMEM_TOTAL>>>(
            combH, combL, WdecIHh, WdecIHl,
            hih, hil, WdecHHh, WdecHHl,
            nullptr, 0, nullptr,
            bDec, c, c, h_out, hoh, hol, nullptr);
        pred_kernel<<<B_, 128>>>(h_out, out_W, out_b, outp, t, x_out);
        { float* tp = h_in; h_in = h_out; h_out = tp; }
        { bf16* tp = hih; hih = hoh; hoh = tp; tp = hil; hil = hol; hol = tp; }
        { float* tp = x_in; x_in = x_out; x_out = tp; }
    }
}

// round 11
// speedup vs baseline: 1.9968x; 1.7196x over previous
#include <cuda_runtime.h>
#include <cuda_bf16.h>
#include <math.h>
#include <stdint.h>

#define B_  1024
#define L_  50
#define D_  4
#define H_  512
#define T_  30
#define N4H 2048
#define CW  516

typedef __nv_bfloat16 bf16;

// ===================== base-ISA PTX helpers (sm_80+ features only) =====================
__device__ __forceinline__ uint32_t smem_u32(const void* p) {
    uint32_t a;
    asm("{ .reg .u64 t; cvta.to.shared.u64 t, %1; cvt.u32.u64 %0, t; }" : "=r"(a) : "l"(p));
    return a;
}
__device__ __forceinline__ void mma16816(float* d, const uint32_t* a, const uint32_t* b) {
    asm volatile(
        "mma.sync.aligned.m16n8k16.row.col.f32.bf16.bf16.f32 "
        "{%0,%1,%2,%3}, {%4,%5,%6,%7}, {%8,%9}, {%0,%1,%2,%3};"
        : "+f"(d[0]), "+f"(d[1]), "+f"(d[2]), "+f"(d[3])
        : "r"(a[0]), "r"(a[1]), "r"(a[2]), "r"(a[3]), "r"(b[0]), "r"(b[1]));
}
__device__ __forceinline__ void ldsm4(uint32_t* r, uint32_t addr) {
    asm volatile("ldmatrix.sync.aligned.m8n8.x4.shared.b16 {%0,%1,%2,%3}, [%4];"
        : "=r"(r[0]), "=r"(r[1]), "=r"(r[2]), "=r"(r[3]) : "r"(addr));
}
#define CP_ASYNC16(sa, gp) \
    asm volatile("cp.async.ca.shared.global [%0], [%1], 16;" :: "r"(sa), "l"(gp) : "memory")
#define CP_COMMIT() asm volatile("cp.async.commit_group;" ::: "memory")

__device__ __forceinline__ float sigf(float x) { return 1.f / (1.f + __expf(-x)); }
__device__ __forceinline__ void bsplit(float v, bf16& hi, bf16& lo) {
    hi = __float2bfloat16(v);
    lo = __float2bfloat16(v - __bfloat162float(hi));
}

// ============================ persistent device state ============================
__device__ __align__(16) float g_hA[B_ * H_];
__device__ __align__(16) float g_hB[B_ * H_];
__device__ __align__(16) bf16  g_hAh[B_ * H_];
__device__ __align__(16) bf16  g_hAl[B_ * H_];
__device__ __align__(16) bf16  g_hBh[B_ * H_];
__device__ __align__(16) bf16  g_hBl[B_ * H_];
__device__ __align__(16) float g_c[B_ * H_];
__device__ __align__(16) float g_enc[B_ * L_ * H_];
__device__ __align__(16) bf16  g_attnH[B_ * H_];
__device__ __align__(16) bf16  g_attnL[B_ * H_];
__device__ __align__(16) bf16  g_combH[B_ * H_];
__device__ __align__(16) bf16  g_combL[B_ * H_];
__device__ __align__(16) float g_xA[B_ * D_];
__device__ __align__(16) float g_xB[B_ * D_];
// gate-permuted weights for fused LSTM epilogue:
// new col n: chunk=n>>4, w=n&15, gate=((w>>3)<<1)|(w&1), unit=chunk*4+((w>>1)&3)
__device__ __align__(16) bf16  g_WencHHh[N4H * H_];
__device__ __align__(16) bf16  g_WencHHl[N4H * H_];
__device__ __align__(16) bf16  g_WdecIHh[N4H * H_];
__device__ __align__(16) bf16  g_WdecIHl[N4H * H_];
__device__ __align__(16) bf16  g_WdecHHh[N4H * H_];
__device__ __align__(16) bf16  g_WdecHHl[N4H * H_];
__device__ __align__(16) float g_WencIH[N4H * D_];
__device__ __align__(16) bf16  g_combWh[H_ * H_];
__device__ __align__(16) bf16  g_combWl[H_ * H_];
__device__ __align__(16) float g_combWsm[H_ * D_];
__device__ float g_bEnc[N4H];
__device__ float g_bDec[N4H];

// ============================ init / repack ============================
__global__ void init_kernel(const float* __restrict__ input) {
    int idx = blockIdx.x * blockDim.x + threadIdx.x;
    if (idx < B_ * H_) {
        g_hA[idx] = 0.f; g_c[idx] = 0.f;
        g_hAh[idx] = __float2bfloat16(0.f); g_hAl[idx] = __float2bfloat16(0.f);
    }
    if (idx < B_ * D_) {
        int b = idx >> 2, d = idx & 3;
        g_xA[idx] = input[b * (L_ * D_) + (L_ - 1) * D_ + d];
    }
}

__global__ void repack_kernel(const float* __restrict__ encHH, const float* __restrict__ encIH,
                              const float* __restrict__ decIH, const float* __restrict__ decHH,
                              const float* __restrict__ combW,
                              const float* __restrict__ eb1, const float* __restrict__ eb2,
                              const float* __restrict__ db1, const float* __restrict__ db2)
{
    int n = blockIdx.x;                          // new row index 0..2047
    int w = n & 15, chunk = n >> 4;
    int gate = ((w >> 3) << 1) | (w & 1);
    int u = chunk * 4 + ((w >> 1) & 3);
    int src = gate * H_ + u;
    for (int k = threadIdx.x; k < H_; k += blockDim.x) {
        bf16 hi, lo;
        bsplit(encHH[src * H_ + k], hi, lo);
        g_WencHHh[n * H_ + k] = hi; g_WencHHl[n * H_ + k] = lo;
        bsplit(decIH[src * H_ + k], hi, lo);
        g_WdecIHh[n * H_ + k] = hi; g_WdecIHl[n * H_ + k] = lo;
        bsplit(decHH[src * H_ + k], hi, lo);
        g_WdecHHh[n * H_ + k] = hi; g_WdecHHl[n * H_ + k] = lo;
        if (n < H_) {
            bsplit(combW[n * CW + D_ + k], hi, lo);      // natural order for comb
            g_combWh[n * H_ + k] = hi; g_combWl[n * H_ + k] = lo;
        }
    }
    if (threadIdx.x < D_) {
        g_WencIH[n * D_ + threadIdx.x] = encIH[src * D_ + threadIdx.x];
        if (n < H_) g_combWsm[n * D_ + threadIdx.x] = combW[n * CW + threadIdx.x];
    }
    if (threadIdx.x == 0) {
        g_bEnc[n] = eb1[src] + eb2[src];
        g_bDec[n] = db1[src] + db2[src];
    }
}

// ============================ HMMA GEMM (+fused epilogue) ============================
// C[64x128] = A(hi/lo bf16, 64xK) @ W(hi/lo bf16, 128xK)^T via 3x mma.sync.m16n8k16
// per k16 (hi*hi + hi*lo + lo*hi), fp32 accum. 8 warps, warp tile 32m x 32n.
// BK=32, cp.async 3-stage ring (prefetch distance 2), 80B-padded rows.
// 2 blocks/SM (96KB smem) -> 16 warps/SM for latency hiding.

#define ROW_B   80
#define A_OFF   0                         // Ah rows 0..63
#define AL_OFF  (64 * ROW_B)              // Al rows 64..127
#define BH_OFF  (128 * ROW_B)             // Bh rows 128..255
#define BL_OFF  (256 * ROW_B)             // Bl rows 256..383
#define STAGE_B (384 * ROW_B)             // 30720 bytes per stage
#define SM_BIAS (3 * STAGE_B)             // 92160
#define SM_XS   (SM_BIAS + 512)           // 64 x 4 floats
#define SM_WS   (SM_XS + 1024)            // 128 x 4 floats
#define SMEM_TOTAL (SM_WS + 2048)         // 95744 bytes

template<int NPASS, bool HAS_SMALL, bool LSTM_EPI, bool WRITE_ENC>
__global__ void __launch_bounds__(256, 2)
mma_kernel(const bf16* __restrict__ A0h, const bf16* __restrict__ A0l,
           const bf16* __restrict__ B0h, const bf16* __restrict__ B0l,
           const bf16* __restrict__ A1h, const bf16* __restrict__ A1l,
           const bf16* __restrict__ B1h, const bf16* __restrict__ B1l,
           const float* __restrict__ Asm, int ldasm, const float* __restrict__ Wsm,
           const float* __restrict__ bias,
           const float* __restrict__ c_in, float* __restrict__ c_out,
           float* __restrict__ h_out, bf16* __restrict__ hh_out, bf16* __restrict__ hl_out,
           float* __restrict__ enc_slot)
{
    extern __shared__ char smem[];
    const uint32_t sb = smem_u32(smem);
    const int tid = threadIdx.x;
    const int wid = tid >> 5, lane = tid & 31;
    const int warp_m = wid & 1, warp_n = wid >> 1;    // 2 x 4 warp grid, 32x32 each
    const int lane8 = lane & 7, sel = lane >> 3;
    const int gID = lane >> 2, tig = lane & 3;
    const int bn = blockIdx.x * 128;
    const int bm = blockIdx.y * 64;

    float* sbias = (float*)(smem + SM_BIAS);
    float* xs    = (float*)(smem + SM_XS);
    float* ws    = (float*)(smem + SM_WS);

    if (tid < 128) sbias[tid] = bias[bn + tid];
    if (HAS_SMALL) {
        if (tid < 64) {
            const float* xr = Asm + (size_t)(bm + tid) * ldasm;
            xs[tid * 4 + 0] = xr[0]; xs[tid * 4 + 1] = xr[1];
            xs[tid * 4 + 2] = xr[2]; xs[tid * 4 + 3] = xr[3];
        } else if (tid < 192) {
            int r = tid - 64;
            float4 v = *reinterpret_cast<const float4*>(&Wsm[(bn + r) * 4]);
            ws[r * 4 + 0] = v.x; ws[r * 4 + 1] = v.y; ws[r * 4 + 2] = v.z; ws[r * 4 + 3] = v.w;
        }
    }

    float acc[2][4][4];
    #pragma unroll
    for (int mt = 0; mt < 2; mt++)
        #pragma unroll
        for (int nt = 0; nt < 4; nt++)
            #pragma unroll
            for (int c = 0; c < 4; c++) acc[mt][nt][c] = 0.f;

    const int NS = NPASS * 16;

    auto load_stage = [&](int buf, int s) {
        const bool p1 = (NPASS == 2) && (s >= 16);
        const bf16* Ah = p1 ? A1h : A0h;
        const bf16* Al = p1 ? A1l : A0l;
        const bf16* Bh = p1 ? B1h : B0h;
        const bf16* Bl = p1 ? B1l : B0l;
        const int k0 = (s & 15) * 32;
        const uint32_t tb = sb + buf * STAGE_B;
        #pragma unroll
        for (int j = 0; j < 6; j++) {
            const int sIdx = j * 256 + tid;
            const int row = sIdx >> 2, seg = sIdx & 3;      // row uniform-range per j
            const bf16* g; int grow;
            if (row < 64)       { g = Ah; grow = bm + row; }
            else if (row < 128) { g = Al; grow = bm + row - 64; }
            else if (row < 256) { g = Bh; grow = bn + row - 128; }
            else                { g = Bl; grow = bn + row - 256; }
            const bf16* gp = g + (size_t)grow * H_ + k0 + seg * 8;
            CP_ASYNC16(tb + row * ROW_B + seg * 16, gp);
        }
        CP_COMMIT();
    };

    auto compute = [&](int buf) {
        const uint32_t tb = sb + buf * STAGE_B;
        #pragma unroll
        for (int kq = 0; kq < 2; kq++) {
            const int kk = kq * 16;
            const int kcol = (kk + ((sel >> 1) << 3)) * 2;
            uint32_t ah[2][4], al[2][4];
            #pragma unroll
            for (int mt = 0; mt < 2; mt++) {
                const int ar = warp_m * 32 + mt * 16 + ((sel & 1) << 3) + lane8;
                uint32_t ra = tb + (uint32_t)(ar * ROW_B) + kcol;
                ldsm4(ah[mt], ra + A_OFF);
                ldsm4(al[mt], ra + AL_OFF);
            }
            const int kcolb = (kk + ((sel & 1) << 3)) * 2;
            uint32_t bh[2][4], bl[2][4];
            #pragma unroll
            for (int p = 0; p < 2; p++) {
                const int br = warp_n * 32 + (2 * p + (sel >> 1)) * 8 + lane8;
                uint32_t rb = tb + (uint32_t)(br * ROW_B) + kcolb;
                ldsm4(bh[p], rb + BH_OFF);
                ldsm4(bl[p], rb + BL_OFF);
            }
            #pragma unroll
            for (int mt = 0; mt < 2; mt++)
                #pragma unroll
                for (int p = 0; p < 2; p++) {
                    mma16816(acc[mt][2 * p],     ah[mt], bh[p]);
                    mma16816(acc[mt][2 * p + 1], ah[mt], bh[p] + 2);
                    mma16816(acc[mt][2 * p],     ah[mt], bl[p]);
                    mma16816(acc[mt][2 * p + 1], ah[mt], bl[p] + 2);
                    mma16816(acc[mt][2 * p],     al[mt], bh[p]);
                    mma16816(acc[mt][2 * p + 1], al[mt], bh[p] + 2);
                }
        }
    };

    load_stage(0, 0);
    if (NS > 1) load_stage(1, 1);
    #pragma unroll 1
    for (int s = 0; s < NS; s++) {
        if (s + 2 < NS) {
            load_stage((s + 2) % 3, s + 2);
            asm volatile("cp.async.wait_group 2;" ::: "memory");
        } else if (s + 1 < NS) {
            asm volatile("cp.async.wait_group 1;" ::: "memory");
        } else {
            asm volatile("cp.async.wait_group 0;" ::: "memory");
        }
        __syncthreads();
        compute(s % 3);
        __syncthreads();
    }

    // -------------------- epilogue --------------------
    if (LSTM_EPI) {
        #pragma unroll
        for (int mt = 0; mt < 2; mt++) {
            #pragma unroll
            for (int rh = 0; rh < 2; rh++) {           // C-fragment row half (+0 / +8)
                const int rl = warp_m * 32 + mt * 16 + gID + rh * 8;
                const int grow = bm + rl;
                const int ci = rh * 2;
                float x0 = 0.f, x1 = 0.f, x2 = 0.f, x3 = 0.f;
                if (HAS_SMALL) {
                    const float* xr = xs + rl * 4;
                    x0 = xr[0]; x1 = xr[1]; x2 = xr[2]; x3 = xr[3];
                }
                #pragma unroll
                for (int k = 0; k < 2; k++) {
                    const int ni = warp_n * 32 + k * 16 + 2 * tig;   // local col of gate i
                    float pi = acc[mt][2 * k][ci]     + sbias[ni];
                    float pf = acc[mt][2 * k][ci + 1] + sbias[ni + 1];
                    float pg = acc[mt][2 * k + 1][ci]     + sbias[ni + 8];
                    float po = acc[mt][2 * k + 1][ci + 1] + sbias[ni + 9];
                    if (HAS_SMALL) {
                        const float* wi = ws + ni * 4;
                        const float* wf = ws + (ni + 1) * 4;
                        const float* wg = ws + (ni + 8) * 4;
                        const float* wo = ws + (ni + 9) * 4;
                        pi += x0 * wi[0] + x1 * wi[1] + x2 * wi[2] + x3 * wi[3];
                        pf += x0 * wf[0] + x1 * wf[1] + x2 * wf[2] + x3 * wf[3];
                        pg += x0 * wg[0] + x1 * wg[1] + x2 * wg[2] + x3 * wg[3];
                        po += x0 * wo[0] + x1 * wo[1] + x2 * wo[2] + x3 * wo[3];
                    }
                    const int u = (bn >> 2) + warp_n * 8 + k * 4 + tig;
                    const int idx = grow * H_ + u;
                    float cold = c_in[idx];
                    float cn = sigf(pf) * cold + sigf(pi) * tanhf(pg);
                    float hn = sigf(po) * tanhf(cn);
                    c_out[idx] = cn;
                    h_out[idx] = hn;
                    bf16 hh, hl; bsplit(hn, hh, hl);
                    hh_out[idx] = hh; hl_out[idx] = hl;
                    if (WRITE_ENC) enc_slot[grow * (L_ * H_) + u] = hn;
                }
            }
        }
    } else {
        #pragma unroll
        for (int mt = 0; mt < 2; mt++) {
            #pragma unroll
            for (int c = 0; c < 4; c++) {
                const int rl = warp_m * 32 + mt * 16 + gID + (c >> 1) * 8;
                const int grow = bm + rl;
                float x0 = 0.f, x1 = 0.f, x2 = 0.f, x3 = 0.f;
                if (HAS_SMALL) {
                    const float* xr = xs + rl * 4;
                    x0 = xr[0]; x1 = xr[1]; x2 = xr[2]; x3 = xr[3];
                }
                #pragma unroll
                for (int nt = 0; nt < 4; nt++) {
                    const int nl = warp_n * 32 + nt * 8 + 2 * tig + (c & 1);
                    float v = acc[mt][nt][c] + sbias[nl];
                    if (HAS_SMALL) {
                        const float* w = ws + nl * 4;
                        v += x0 * w[0] + x1 * w[1] + x2 * w[2] + x3 * w[3];
                    }
                    v = fmaxf(v, 0.f);
                    const int idx = grow * H_ + bn + nl;
                    bf16 hh, hl; bsplit(v, hh, hl);
                    hh_out[idx] = hh; hl_out[idx] = hl;
                }
            }
        }
    }
}

// ============================ attention (fp32) ============================
// h_r[b,k] = h[2k + (b>=512), b & 511]  (reference's reshape/transpose quirk)
__global__ void __launch_bounds__(256)
attn_kernel(const float* __restrict__ x, const float* __restrict__ h,
            const float* __restrict__ attn_W, const float* __restrict__ attn_b,
            const float* __restrict__ enc, bf16* __restrict__ outH, bf16* __restrict__ outL)
{
    __shared__ float v[H_ + D_];
    __shared__ float wts[64];
    const int b = blockIdx.x;
    const int tid = threadIdx.x;

    if (tid < D_) v[tid] = x[b * D_ + tid];
    {
        int brow = b >> 9, bcol = b & 511;
        for (int k = tid; k < H_; k += 256)
            v[D_ + k] = h[(2 * k + brow) * H_ + bcol];
    }
    __syncthreads();

    const int warp = tid >> 5, lane = tid & 31;
    for (int l = warp; l < L_; l += 8) {
        const float* wrow = attn_W + l * (H_ + D_);
        float s = 0.f;
        for (int k = lane; k < H_ + D_; k += 32) s += v[k] * wrow[k];
        #pragma unroll
        for (int off = 16; off; off >>= 1) s += __shfl_xor_sync(0xffffffffu, s, off);
        if (lane == 0) wts[l] = s + attn_b[l];
    }
    __syncthreads();

    if (tid < 32) {
        float v1 = (tid < L_) ? wts[tid] : -1e30f;
        float v2 = (tid + 32 < L_) ? wts[tid + 32] : -1e30f;
        float m = fmaxf(v1, v2);
        #pragma unroll
        for (int off = 16; off; off >>= 1) m = fmaxf(m, __shfl_xor_sync(0xffffffffu, m, off));
        float e1 = (tid < L_) ? __expf(v1 - m) : 0.f;
        float e2 = (tid + 32 < L_) ? __expf(v2 - m) : 0.f;
        float s = e1 + e2;
        #pragma unroll
        for (int off = 16; off; off >>= 1) s += __shfl_xor_sync(0xffffffffu, s, off);
        float inv = 1.f / s;
        if (tid < L_) wts[tid] = e1 * inv;
        if (tid + 32 < L_) wts[tid + 32] = e2 * inv;
    }
    __syncthreads();

    const float* e = enc + (size_t)b * (L_ * H_);
    for (int j = tid; j < H_; j += 256) {
        float s = 0.f;
        #pragma unroll
        for (int l = 0; l < L_; l++) s += wts[l] * e[l * H_ + j];
        bf16 hi, lo; bsplit(s, hi, lo);
        outH[b * H_ + j] = hi; outL[b * H_ + j] = lo;
    }
}

// ============================ pred ============================
__global__ void pred_kernel(const float* __restrict__ h, const float* __restrict__ out_W,
                            const float* __restrict__ out_b, float* __restrict__ out,
                            int t, float* __restrict__ x_next)
{
    const int b = blockIdx.x;
    const int warp = threadIdx.x >> 5, lane = threadIdx.x & 31;
    const float* hr = h + b * H_;
    const float* w = out_W + warp * H_;
    float s = 0.f;
    #pragma unroll
    for (int k = lane; k < H_; k += 32) s += hr[k] * w[k];
    #pragma unroll
    for (int off = 16; off; off >>= 1) s += __shfl_xor_sync(0xffffffffu, s, off);
    if (lane == 0) {
        float p = s + out_b[warp];
        out[(b * T_ + t) * D_ + warp] = p;
        x_next[b * D_ + warp] = p;
    }
}

// ============================ launch ============================
extern "C" void kernel_launch(void* const* d_in, const int* in_sizes, int n_in,
                              void* d_out, int out_size)
{
    int base = (n_in >= 16 && in_sizes[1] == 1) ? 2 : 1;

    const float* input    = (const float*)d_in[0];
    const float* enc_W_ih = (const float*)d_in[base + 0];
    const float* enc_W_hh = (const float*)d_in[base + 1];
    const float* enc_b_ih = (const float*)d_in[base + 2];
    const float* enc_b_hh = (const float*)d_in[base + 3];
    const float* attn_W   = (const float*)d_in[base + 4];
    const float* attn_b   = (const float*)d_in[base + 5];
    const float* comb_W   = (const float*)d_in[base + 6];
    const float* comb_b   = (const float*)d_in[base + 7];
    const float* dec_W_ih = (const float*)d_in[base + 8];
    const float* dec_W_hh = (const float*)d_in[base + 9];
    const float* dec_b_ih = (const float*)d_in[base + 10];
    const float* dec_b_hh = (const float*)d_in[base + 11];
    const float* out_W    = (const float*)d_in[base + 12];
    const float* out_b    = (const float*)d_in[base + 13];
    float* outp = (float*)d_out;

    float *hA, *hB, *c, *enc, *xA, *xB, *WencIH, *combWsm, *bEnc, *bDec;
    bf16 *hAh, *hAl, *hBh, *hBl, *attnH, *attnL, *combH, *combL;
    bf16 *WencHHh, *WencHHl, *WdecIHh, *WdecIHl, *WdecHHh, *WdecHHl, *combWh, *combWl;
    cudaGetSymbolAddress((void**)&hA, g_hA);
    cudaGetSymbolAddress((void**)&hB, g_hB);
    cudaGetSymbolAddress((void**)&hAh, g_hAh);
    cudaGetSymbolAddress((void**)&hAl, g_hAl);
    cudaGetSymbolAddress((void**)&hBh, g_hBh);
    cudaGetSymbolAddress((void**)&hBl, g_hBl);
    cudaGetSymbolAddress((void**)&c, g_c);
    cudaGetSymbolAddress((void**)&enc, g_enc);
    cudaGetSymbolAddress((void**)&attnH, g_attnH);
    cudaGetSymbolAddress((void**)&attnL, g_attnL);
    cudaGetSymbolAddress((void**)&combH, g_combH);
    cudaGetSymbolAddress((void**)&combL, g_combL);
    cudaGetSymbolAddress((void**)&xA, g_xA);
    cudaGetSymbolAddress((void**)&xB, g_xB);
    cudaGetSymbolAddress((void**)&WencHHh, g_WencHHh);
    cudaGetSymbolAddress((void**)&WencHHl, g_WencHHl);
    cudaGetSymbolAddress((void**)&WdecIHh, g_WdecIHh);
    cudaGetSymbolAddress((void**)&WdecIHl, g_WdecIHl);
    cudaGetSymbolAddress((void**)&WdecHHh, g_WdecHHh);
    cudaGetSymbolAddress((void**)&WdecHHl, g_WdecHHl);
    cudaGetSymbolAddress((void**)&WencIH, g_WencIH);
    cudaGetSymbolAddress((void**)&combWh, g_combWh);
    cudaGetSymbolAddress((void**)&combWl, g_combWl);
    cudaGetSymbolAddress((void**)&combWsm, g_combWsm);
    cudaGetSymbolAddress((void**)&bEnc, g_bEnc);
    cudaGetSymbolAddress((void**)&bDec, g_bDec);

    cudaFuncSetAttribute(mma_kernel<1, true, true, true>,
                         cudaFuncAttributeMaxDynamicSharedMemorySize, SMEM_TOTAL);
    cudaFuncSetAttribute(mma_kernel<1, true, false, false>,
                         cudaFuncAttributeMaxDynamicSharedMemorySize, SMEM_TOTAL);
    cudaFuncSetAttribute(mma_kernel<2, false, true, false>,
                         cudaFuncAttributeMaxDynamicSharedMemorySize, SMEM_TOTAL);

    init_kernel<<<(B_ * H_ + 255) / 256, 256>>>(input);
    repack_kernel<<<N4H, 256>>>(enc_W_hh, enc_W_ih, dec_W_ih, dec_W_hh, comb_W,
                                enc_b_ih, enc_b_hh, dec_b_ih, dec_b_hh);

    const dim3 grid_gates(N4H / 128, B_ / 64);   // 16 x 16 = 256 blocks
    const dim3 grid_comb(H_ / 128, B_ / 64);     // 4 x 16 = 64 blocks

    // ---------------- encoder ----------------
    float *h_in = hA, *h_out = hB;
    bf16 *hih = hAh, *hil = hAl, *hoh = hBh, *hol = hBl;
    for (int t = 0; t < L_; t++) {
        mma_kernel<1, true, true, true><<<grid_gates, 256, SMEM_TOTAL>>>(
            hih, hil, WencHHh, WencHHl,
            nullptr, nullptr, nullptr, nullptr,
            input + t * D_, L_ * D_, WencIH,
            bEnc, c, c, h_out, hoh, hol, enc + t * H_);
        { float* tp = h_in; h_in = h_out; h_out = tp; }
        { bf16* tp = hih; hih = hoh; hoh = tp; tp = hil; hil = hol; hol = tp; }
    }

    // ---------------- decoder ----------------
    float *x_in = xA, *x_out = xB;
    for (int t = 0; t < T_; t++) {
        attn_kernel<<<B_, 256>>>(x_in, h_in, attn_W, attn_b, enc, attnH, attnL);
        mma_kernel<1, true, false, false><<<grid_comb, 256, SMEM_TOTAL>>>(
            attnH, attnL, combWh, combWl,
            nullptr, nullptr, nullptr, nullptr,
            x_in, D_, combWsm,
            comb_b, nullptr, nullptr, nullptr, combH, combL, nullptr);
        mma_kernel<2, false, true, false><<<grid_gates, 256, SMEM_TOTAL>>>(
            combH, combL, WdecIHh, WdecIHl,
            hih, hil, WdecHHh, WdecHHl,
            nullptr, 0, nullptr,
            bDec, c, c, h_out, hoh, hol, nullptr);
        pred_kernel<<<B_, 128>>>(h_out, out_W, out_b, outp, t, x_out);
        { float* tp = h_in; h_in = h_out; h_out = tp; }
        { bf16* tp = hih; hih = hoh; hoh = tp; tp = hil; hil = hol; hol = tp; }
        { float* tp = x_in; x_in = x_out; x_out = tp; }
    }
}